// round 15
// baseline (speedup 1.0000x reference)
#include <cuda_runtime.h>
#include <math.h>

#define BB 64
#define CC 3
#define HH 640
#define WW 640
#define PH 128
#define PW 128

struct BatchParams {
    float y0, x0, sh, sw, inv_sh, inv_sw, co, si;
};

__device__ __forceinline__ void ldg256_cs(const float4* p, float4 &a, float4 &b) {
    asm volatile("ld.global.cs.v8.f32 {%0,%1,%2,%3,%4,%5,%6,%7}, [%8];"
        : "=f"(a.x), "=f"(a.y), "=f"(a.z), "=f"(a.w),
          "=f"(b.x), "=f"(b.y), "=f"(b.z), "=f"(b.w)
        : "l"(p));
}

__device__ __forceinline__ void stg256_cs(float4* p, const float4 &a, const float4 &b) {
    asm volatile("st.global.cs.v8.f32 [%0], {%1,%2,%3,%4,%5,%6,%7,%8};"
        :: "l"(p),
           "f"(a.x), "f"(a.y), "f"(a.z), "f"(a.w),
           "f"(b.x), "f"(b.y), "f"(b.z), "f"(b.w)
        : "memory");
}

__global__ __launch_bounds__(256) void patch_kernel(
    const float4* __restrict__ images,
    const float*  __restrict__ patch,
    const float*  __restrict__ angles,
    const float*  __restrict__ scales,
    const float*  __restrict__ ux,
    const float*  __restrict__ uy,
    float4*       __restrict__ out)
{
    constexpr int SW8  = WW / 8;        // 80 strips per row
    constexpr int SIMG = HH * SW8;      // 51200 strips per batch (div by 256)
    constexpr int ROWQ = WW / 4;        // 160 float4 per row
    constexpr int QC   = HH * ROWQ;     // 102400 float4 per channel plane

    __shared__ BatchParams sp;

    int tid = blockIdx.x * 256 + threadIdx.x;
    int b   = blockIdx.x / (SIMG / 256);          // uniform per block
    int rem = tid - b * SIMG;
    int y   = rem / SW8;
    int xs  = rem - y * SW8;

    if (threadIdx.x == 0) {
        float s  = scales[b];
        float sh = floorf((float)PH * s);
        float sw = floorf((float)PW * s);
        BatchParams p;
        p.sh = sh; p.sw = sw;
        p.y0 = floorf(uy[b] * ((float)HH - sh));
        p.x0 = floorf(ux[b] * ((float)WW - sw));
        p.inv_sh = (float)PH / sh;
        p.inv_sw = (float)PW / sw;
        float th = angles[b] * (float)(M_PI / 180.0);
        p.co = cosf(th);
        p.si = sinf(th);
        sp = p;
    }
    __syncthreads();

    float sh = sp.sh, sw = sp.sw;
    float yl  = (float)y - sp.y0;
    float xls = (float)(xs * 8) - sp.x0;
    bool yin  = (yl >= 0.0f) & (yl < sh);
    bool xin  = (xls + 7.0f >= 0.0f) & (xls < sw);

    int q0 = b * (CC * QC) + y * ROWQ + xs * 2;   // float4 index, 32B-aligned

    if (!(yin & xin)) {
        // Fast path: 3 x LDG.256 -> 3 x STG.256 (96B/thread, half the wavefronts)
        float4 a0, a1, b0, b1, c0, c1;
        ldg256_cs(images + q0,          a0, a1);
        ldg256_cs(images + q0 + QC,     b0, b1);
        ldg256_cs(images + q0 + 2 * QC, c0, c1);
        stg256_cs(out + q0,          a0, a1);
        stg256_cs(out + q0 + QC,     b0, b1);
        stg256_cs(out + q0 + 2 * QC, c0, c1);
        return;
    }

    // Slow path: two quads sequentially (register-contained, R7 structure)
    const float cy = (float)(PH - 1) * 0.5f;
    const float cx = (float)(PW - 1) * 0.5f;
    float co = sp.co, si = sp.si;
    float yr   = (yl + 0.5f) * sp.inv_sh - 0.5f;
    float dy   = yr - cy;
    float sidy = si * dy;
    float cody = co * dy;
    float inv_sw = sp.inv_sw;

    #pragma unroll 1
    for (int j = 0; j < 2; j++) {
        int   qj  = q0 + j;
        float xl0 = xls + (float)(4 * j);

        if ((xl0 + 3.0f < 0.0f) | (xl0 >= sw)) {
            __stcs(out + qj,          __ldcs(images + qj));
            __stcs(out + qj + QC,     __ldcs(images + qj + QC));
            __stcs(out + qj + 2 * QC, __ldcs(images + qj + 2 * QC));
            continue;
        }

        bool all_in = (xl0 >= 0.0f) & (xl0 + 3.0f < sw);
        float img[3][4];
        if (!all_in) {
            float4 v0 = __ldcs(images + qj);
            float4 v1 = __ldcs(images + qj + QC);
            float4 v2 = __ldcs(images + qj + 2 * QC);
            img[0][0]=v0.x; img[0][1]=v0.y; img[0][2]=v0.z; img[0][3]=v0.w;
            img[1][0]=v1.x; img[1][1]=v1.y; img[1][2]=v1.z; img[1][3]=v1.w;
            img[2][0]=v2.x; img[2][1]=v2.y; img[2][2]=v2.z; img[2][3]=v2.w;
        }
        float res[3][4];

        #pragma unroll
        for (int i = 0; i < 4; i++) {
            float xl  = xl0 + (float)i;
            bool  vld = (xl >= 0.0f) & (xl < sw);

            if (!vld) {
                res[0][i] = img[0][i];
                res[1][i] = img[1][i];
                res[2][i] = img[2][i];
                continue;
            }

            float xr = (xl + 0.5f) * inv_sw - 0.5f;
            float dx = xr - cx;
            float xp =  co * dx + sidy + cx;
            float yp = -si * dx + cody + cy;

            float fy = floorf(yp);
            float fx = floorf(xp);
            float wy = yp - fy;
            float wx = xp - fx;
            int yi = (int)fy;
            int xi = (int)fx;

            bool y0in = (yi >= 0)  & (yi <  PH);
            bool y1in = (yi >= -1) & (yi <  PH - 1);
            bool x0in = (xi >= 0)  & (xi <  PW);
            bool x1in = (xi >= -1) & (xi <  PW - 1);

            int yc0 = min(max(yi,     0), PH - 1);
            int yc1 = min(max(yi + 1, 0), PH - 1);
            int xc0 = min(max(xi,     0), PW - 1);
            int xc1 = min(max(xi + 1, 0), PW - 1);

            float w00 = (1.0f - wy) * (1.0f - wx) * ((y0in & x0in) ? 1.0f : 0.0f);
            float w01 = (1.0f - wy) * wx          * ((y0in & x1in) ? 1.0f : 0.0f);
            float w10 = wy * (1.0f - wx)          * ((y1in & x0in) ? 1.0f : 0.0f);
            float w11 = wy * wx                   * ((y1in & x1in) ? 1.0f : 0.0f);

            int o00 = yc0 * PW + xc0;
            int o01 = yc0 * PW + xc1;
            int o10 = yc1 * PW + xc0;
            int o11 = yc1 * PW + xc1;

            #pragma unroll
            for (int c = 0; c < 3; c++) {
                const float* pc = patch + c * (PH * PW);
                res[c][i] = w00 * __ldg(pc + o00)
                          + w01 * __ldg(pc + o01)
                          + w10 * __ldg(pc + o10)
                          + w11 * __ldg(pc + o11);
            }
        }

        __stcs(out + qj,          make_float4(res[0][0], res[0][1], res[0][2], res[0][3]));
        __stcs(out + qj + QC,     make_float4(res[1][0], res[1][1], res[1][2], res[1][3]));
        __stcs(out + qj + 2 * QC, make_float4(res[2][0], res[2][1], res[2][2], res[2][3]));
    }
}

extern "C" void kernel_launch(void* const* d_in, const int* in_sizes, int n_in,
                              void* d_out, int out_size) {
    const float* images = (const float*)d_in[0];
    const float* patch  = (const float*)d_in[1];
    const float* angles = (const float*)d_in[2];
    const float* scales = (const float*)d_in[3];
    const float* ux     = (const float*)d_in[4];
    const float* uy     = (const float*)d_in[5];
    float* out = (float*)d_out;

    constexpr int STRIPS = BB * HH * (WW / 8);   // 3,276,800
    int blocks = STRIPS / 256;                   // 12,800
    patch_kernel<<<blocks, 256>>>(
        (const float4*)images, patch, angles, scales, ux, uy, (float4*)out);
}

// round 16
// speedup vs baseline: 1.0342x; 1.0342x over previous
#include <cuda_runtime.h>
#include <math.h>

#define BB 64
#define CC 3
#define HH 640
#define WW 640
#define PH 128
#define PW 128

struct BatchParams {
    float y0, x0, sh, sw, inv_sh, inv_sw, co, si;
};

__global__ __launch_bounds__(256) void patch_kernel(
    const float4* __restrict__ images,
    const float*  __restrict__ patch,
    const float*  __restrict__ angles,
    const float*  __restrict__ scales,
    const float*  __restrict__ ux,
    const float*  __restrict__ uy,
    float4*       __restrict__ out)
{
    constexpr int QW   = WW / 4;        // 160 quads per row
    constexpr int QIMG = HH * QW;       // 102400 quads per channel (divisible by 256)

    __shared__ BatchParams sp;

    int tid = blockIdx.x * 256 + threadIdx.x;
    int b   = blockIdx.x / (QIMG / 256);          // uniform per block
    int rem = tid - b * QIMG;
    int y   = rem / QW;
    int xq  = rem - y * QW;

    if (threadIdx.x == 0) {
        float s  = scales[b];
        float sh = floorf((float)PH * s);
        float sw = floorf((float)PW * s);
        BatchParams p;
        p.sh = sh; p.sw = sw;
        p.y0 = floorf(uy[b] * ((float)HH - sh));
        p.x0 = floorf(ux[b] * ((float)WW - sw));
        p.inv_sh = (float)PH / sh;
        p.inv_sw = (float)PW / sw;
        float th = angles[b] * (float)(M_PI / 180.0);
        p.co = cosf(th);
        p.si = sinf(th);
        sp = p;
    }
    __syncthreads();
    BatchParams p = sp;

    float yl  = (float)y - p.y0;
    float xl0 = (float)(xq * 4) - p.x0;
    bool yin  = (yl >= 0.0f) & (yl < p.sh);
    bool xin  = (xl0 + 3.0f >= 0.0f) & (xl0 < p.sw);

    int q0 = b * (CC * QIMG) + y * QW + xq;   // float4 index of channel 0

    if (!(yin & xin)) {
        // Fast path: streaming copy (evict-first both directions)
        float4 v0 = __ldcs(images + q0);
        float4 v1 = __ldcs(images + q0 + QIMG);
        float4 v2 = __ldcs(images + q0 + 2 * QIMG);
        __stcs(out + q0,            v0);
        __stcs(out + q0 + QIMG,     v1);
        __stcs(out + q0 + 2 * QIMG, v2);
        return;
    }

    // Slow path
    bool all_in = (xl0 >= 0.0f) & (xl0 + 3.0f < p.sw);

    float img[3][4];
    if (!all_in) {
        float4 v0 = __ldcs(images + q0);
        float4 v1 = __ldcs(images + q0 + QIMG);
        float4 v2 = __ldcs(images + q0 + 2 * QIMG);
        img[0][0]=v0.x; img[0][1]=v0.y; img[0][2]=v0.z; img[0][3]=v0.w;
        img[1][0]=v1.x; img[1][1]=v1.y; img[1][2]=v1.z; img[1][3]=v1.w;
        img[2][0]=v2.x; img[2][1]=v2.y; img[2][2]=v2.z; img[2][3]=v2.w;
    }
    float res[3][4];

    const float cy = (float)(PH - 1) * 0.5f;
    const float cx = (float)(PW - 1) * 0.5f;
    float yr   = (yl + 0.5f) * p.inv_sh - 0.5f;
    float dy   = yr - cy;
    float sidy = p.si * dy;
    float cody = p.co * dy;

    #pragma unroll
    for (int i = 0; i < 4; i++) {
        float xl  = xl0 + (float)i;
        bool  vld = (xl >= 0.0f) & (xl < p.sw);

        if (!vld) {
            res[0][i] = img[0][i];
            res[1][i] = img[1][i];
            res[2][i] = img[2][i];
            continue;
        }

        float xr = (xl + 0.5f) * p.inv_sw - 0.5f;
        float dx = xr - cx;
        float xp =  p.co * dx + sidy + cx;
        float yp = -p.si * dx + cody + cy;

        float fy = floorf(yp);
        float fx = floorf(xp);
        float wy = yp - fy;
        float wx = xp - fx;
        int yi = (int)fy;
        int xi = (int)fx;

        bool y0in = (yi >= 0)  & (yi <  PH);
        bool y1in = (yi >= -1) & (yi <  PH - 1);
        bool x0in = (xi >= 0)  & (xi <  PW);
        bool x1in = (xi >= -1) & (xi <  PW - 1);

        int yc0 = min(max(yi,     0), PH - 1);
        int yc1 = min(max(yi + 1, 0), PH - 1);
        int xc0 = min(max(xi,     0), PW - 1);
        int xc1 = min(max(xi + 1, 0), PW - 1);

        float w00 = (1.0f - wy) * (1.0f - wx) * ((y0in & x0in) ? 1.0f : 0.0f);
        float w01 = (1.0f - wy) * wx          * ((y0in & x1in) ? 1.0f : 0.0f);
        float w10 = wy * (1.0f - wx)          * ((y1in & x0in) ? 1.0f : 0.0f);
        float w11 = wy * wx                   * ((y1in & x1in) ? 1.0f : 0.0f);

        int o00 = yc0 * PW + xc0;
        int o01 = yc0 * PW + xc1;
        int o10 = yc1 * PW + xc0;
        int o11 = yc1 * PW + xc1;

        #pragma unroll
        for (int c = 0; c < 3; c++) {
            const float* pc = patch + c * (PH * PW);
            res[c][i] = w00 * __ldg(pc + o00)
                      + w01 * __ldg(pc + o01)
                      + w10 * __ldg(pc + o10)
                      + w11 * __ldg(pc + o11);
        }
    }

    float4 r0 = make_float4(res[0][0], res[0][1], res[0][2], res[0][3]);
    float4 r1 = make_float4(res[1][0], res[1][1], res[1][2], res[1][3]);
    float4 r2 = make_float4(res[2][0], res[2][1], res[2][2], res[2][3]);
    __stcs(out + q0,            r0);
    __stcs(out + q0 + QIMG,     r1);
    __stcs(out + q0 + 2 * QIMG, r2);
}

extern "C" void kernel_launch(void* const* d_in, const int* in_sizes, int n_in,
                              void* d_out, int out_size) {
    const float* images = (const float*)d_in[0];
    const float* patch  = (const float*)d_in[1];
    const float* angles = (const float*)d_in[2];
    const float* scales = (const float*)d_in[3];
    const float* ux     = (const float*)d_in[4];
    const float* uy     = (const float*)d_in[5];
    float* out = (float*)d_out;

    constexpr int QUADS = BB * HH * (WW / 4);   // 6,553,600
    int blocks = QUADS / 256;                   // 25,600
    patch_kernel<<<blocks, 256>>>(
        (const float4*)images, patch, angles, scales, ux, uy, (float4*)out);
}